// round 1
// baseline (speedup 1.0000x reference)
#include <cuda_runtime.h>
#include <math.h>

// ---------------------------------------------------------------------------
// QPSpeedPlanning: conv(3->32,3x3)+relu+pool2 -> conv(32->64,3x3)+relu+pool2
//                  -> FC(9219->6)+relu -> 2x2 SVD clip -> 4x4 KKT solve
// Shapes: x (1024, 8751); image 3x54x54; h1 32x26x26; h2 64x12x12; out (1024,2)
// ---------------------------------------------------------------------------

#define NB 1024

// Scratch (device globals: no allocation allowed in kernel_launch)
__device__ float g_h1[NB * 32 * 26 * 26];   // ~88.6 MB
__device__ float g_h2[NB * 64 * 12 * 12];   // ~37.7 MB

// One task = (8 output channels) x (1 pooled row x 2 pooled cols)
// = conv region 2 rows x 4 cols, input patch 4x6, 64 accumulators.
template<int IC, int IN_W, int OUT_W, int UNROLL>
__device__ __forceinline__ void conv_pool_task(
    const float* __restrict__ s_in,
    const float* __restrict__ s_w,
    const float* __restrict__ s_b,
    float* __restrict__ out,
    int ocg, int ty, int tx)
{
    const int IN_PLANE = IN_W * IN_W;
    const int y0 = 2 * ty, x0 = 4 * tx;
    float acc[8][8];
#pragma unroll
    for (int i = 0; i < 8; i++)
#pragma unroll
        for (int j = 0; j < 8; j++) acc[i][j] = 0.f;

#pragma unroll UNROLL
    for (int ic = 0; ic < IC; ic++) {
        float p[4][6];
        const float* ip = s_in + ic * IN_PLANE + y0 * IN_W + x0;
#pragma unroll
        for (int r = 0; r < 4; r++)
#pragma unroll
            for (int c = 0; c < 6; c++)
                p[r][c] = ip[r * IN_W + c];
#pragma unroll
        for (int o = 0; o < 8; o++) {
            const float* wp = s_w + ((ocg * 8 + o) * IC + ic) * 9;
            float w00 = wp[0], w01 = wp[1], w02 = wp[2];
            float w10 = wp[3], w11 = wp[4], w12 = wp[5];
            float w20 = wp[6], w21 = wp[7], w22 = wp[8];
#pragma unroll
            for (int r = 0; r < 2; r++)
#pragma unroll
                for (int c = 0; c < 4; c++) {
                    float s = acc[o][r * 4 + c];
                    s = fmaf(w00, p[r][c],     s);
                    s = fmaf(w01, p[r][c + 1], s);
                    s = fmaf(w02, p[r][c + 2], s);
                    s = fmaf(w10, p[r + 1][c],     s);
                    s = fmaf(w11, p[r + 1][c + 1], s);
                    s = fmaf(w12, p[r + 1][c + 2], s);
                    s = fmaf(w20, p[r + 2][c],     s);
                    s = fmaf(w21, p[r + 2][c + 1], s);
                    s = fmaf(w22, p[r + 2][c + 2], s);
                    acc[o][r * 4 + c] = s;
                }
        }
    }

    // pool (max over 2x2 conv outputs) then +bias then relu (monotone => legal order)
#pragma unroll
    for (int o = 0; o < 8; o++) {
        int oc = ocg * 8 + o;
        float bs = s_b[oc];
#pragma unroll
        for (int pc = 0; pc < 2; pc++) {
            float m = fmaxf(fmaxf(acc[o][2 * pc], acc[o][2 * pc + 1]),
                            fmaxf(acc[o][4 + 2 * pc], acc[o][4 + 2 * pc + 1]));
            out[(oc * OUT_W + ty) * OUT_W + 2 * tx + pc] = fmaxf(m + bs, 0.f);
        }
    }
}

// ---------------- conv1: 3x54x54 -> 32x26x26 (pooled) ----------------
__global__ __launch_bounds__(256, 1) void conv1_kernel(
    const float* __restrict__ x, const float* __restrict__ w,
    const float* __restrict__ bias)
{
    __shared__ float s_in[3 * 54 * 54];   // 8748
    __shared__ float s_w[32 * 3 * 9];     // 864
    __shared__ float s_b[32];
    int b = blockIdx.x, tid = threadIdx.x;
    const float* xb = x + b * 8751;
    for (int i = tid; i < 8748; i += 256) s_in[i] = xb[i];
    for (int i = tid; i < 864; i += 256) s_w[i] = w[i];
    if (tid < 32) s_b[tid] = bias[tid];
    __syncthreads();

    float* out = g_h1 + b * (32 * 26 * 26);
    // tasks: 26 pooled rows * 13 col-pairs * 4 oc-groups = 1352
    for (int t = tid; t < 1352; t += 256) {
        int ocg = t / 338;
        int rem = t - ocg * 338;
        int ty = rem / 13, tx = rem - ty * 13;
        conv_pool_task<3, 54, 26, 3>(s_in, s_w, s_b, out, ocg, ty, tx);
    }
}

// ---------------- conv2: 32x26x26 -> 64x12x12 (pooled) ----------------
__global__ __launch_bounds__(288, 1) void conv2_kernel(
    const float* __restrict__ w, const float* __restrict__ bias)
{
    extern __shared__ float sm[];
    float* s_in = sm;                 // 21632 floats
    float* s_w  = sm + 21632;         // 18432 floats
    float* s_b  = s_w + 18432;        // 64 floats
    int b = blockIdx.x, tid = threadIdx.x;
    const float* hin = g_h1 + b * (32 * 26 * 26);
    for (int i = tid; i < 21632; i += 288) s_in[i] = hin[i];
    for (int i = tid; i < 18432; i += 288) s_w[i] = w[i];
    if (tid < 64) s_b[tid] = bias[tid];
    __syncthreads();

    float* out = g_h2 + b * (64 * 12 * 12);
    // tasks: 12 pooled rows * 6 col-pairs * 8 oc-groups = 576 ; 288 thr -> 2 each
    for (int t = tid; t < 576; t += 288) {
        int ocg = t / 72;
        int rem = t - ocg * 72;
        int ty = rem / 6, tx = rem - ty * 6;
        conv_pool_task<32, 26, 12, 1>(s_in, s_w, s_b, out, ocg, ty, tx);
    }
}

// ---------------- FC + relu + SVD-clip + KKT solve ----------------
__global__ __launch_bounds__(256, 1) void fc_solve_kernel(
    const float* __restrict__ x, const float* __restrict__ fw,
    const float* __restrict__ fb, float* __restrict__ out)
{
    int b = blockIdx.x, tid = threadIdx.x;
    const float* h2 = g_h2 + b * 9216;
    float p[6] = {0.f, 0.f, 0.f, 0.f, 0.f, 0.f};
    for (int j = tid; j < 9216; j += 256) {
        float hv = h2[j];
#pragma unroll
        for (int o = 0; o < 6; o++)
            p[o] = fmaf(hv, fw[o * 9219 + j], p[o]);
    }
#pragma unroll
    for (int o = 0; o < 6; o++)
#pragma unroll
        for (int off = 16; off > 0; off >>= 1)
            p[o] += __shfl_down_sync(0xffffffffu, p[o], off);

    __shared__ float red[8][6];
    int warp = tid >> 5, lane = tid & 31;
    if (lane == 0) {
#pragma unroll
        for (int o = 0; o < 6; o++) red[warp][o] = p[o];
    }
    __syncthreads();

    if (tid == 0) {
        float y[6];
#pragma unroll
        for (int o = 0; o < 6; o++) {
            float s = 0.f;
            for (int wi = 0; wi < 8; wi++) s += red[wi][o];
            for (int e = 0; e < 3; e++)
                s = fmaf(x[b * 8751 + 8748 + e], fw[o * 9219 + 9216 + e], s);
            s += fb[o];
            y[o] = fmaxf(s, 0.f);
        }

        // A = [[y0, y1],[y2, y3]], b = [y4, y5]
        double a11 = y[0], a12 = y[1], a21 = y[2], a22 = y[3];
        double bb1 = y[4], bb2 = y[5];

        // Closed-form 2x2 SVD in rotation form: A = R(ph) diag(sx, sy) R(th)
        double E = 0.5 * (a11 + a22), F = 0.5 * (a11 - a22);
        double G = 0.5 * (a21 + a12), H = 0.5 * (a21 - a12);
        double Qv = sqrt(E * E + H * H), Rv = sqrt(F * F + G * G);
        double sx = Qv + Rv, sy = Qv - Rv;  // sx = sigma_max >= |sy| = sigma_min

        double B11, B12, B21, B22;
        if (sx <= 0.0) {
            // zero matrix: S_p = 0.01, U = Vh = I  =>  A_p = 0.01 I
            B11 = 0.01; B22 = 0.01; B12 = 0.0; B21 = 0.0;
        } else {
            double sig2 = fabs(sy);
            double lo = 0.1 * sx;                 // smax / EPSILON
            double c2 = sig2 < lo ? lo : sig2;    // clip (upper clip is no-op)
            double s2 = (sy < 0.0) ? -c2 : c2;    // keep sign convention of sy
            double ag1 = atan2(G, F), ag2 = atan2(H, E);
            double th = 0.5 * (ag2 - ag1), ph = 0.5 * (ag2 + ag1);
            double ct = cos(th), st = sin(th), cp = cos(ph), sp = sin(ph);
            // A_p = R(ph) * diag(sx, s2) * R(th)
            B11 =  cp * sx * ct - sp * s2 * st;
            B12 = -cp * sx * st - sp * s2 * ct;
            B21 =  sp * sx * ct + cp * s2 * st;
            B22 = -sp * sx * st + cp * s2 * ct;
        }

        // KKT solve via Schur complement. Q = diag(1, 0.5), p = (0, -1000)
        // K = B Q^-1 B^T,  K lam = B Q^-1 (-p) - b,  z = Q^-1 (-p - B^T lam)
        double K11 = B11 * B11 + 2.0 * B12 * B12;
        double K12 = B11 * B21 + 2.0 * B12 * B22;
        double K22 = B21 * B21 + 2.0 * B22 * B22;
        double w1 = 2000.0 * B12 - bb1;
        double w2 = 2000.0 * B22 - bb2;
        double det = K11 * K22 - K12 * K12;
        double l1 = (K22 * w1 - K12 * w2) / det;
        double l2 = (K11 * w2 - K12 * w1) / det;
        double z1 = -(B11 * l1 + B21 * l2);
        double z2 = 2.0 * (1000.0 - (B12 * l1 + B22 * l2));
        out[b * 2 + 0] = (float)z1;
        out[b * 2 + 1] = (float)z2;
    }
}

extern "C" void kernel_launch(void* const* d_in, const int* in_sizes, int n_in,
                              void* d_out, int out_size) {
    const float* x   = (const float*)d_in[0];
    const float* c1w = (const float*)d_in[1];
    const float* c1b = (const float*)d_in[2];
    const float* c2w = (const float*)d_in[3];
    const float* c2b = (const float*)d_in[4];
    const float* fw  = (const float*)d_in[5];
    const float* fb  = (const float*)d_in[6];
    float* out = (float*)d_out;

    const int smem2 = (21632 + 18432 + 64) * (int)sizeof(float);  // 160512 B
    cudaFuncSetAttribute((const void*)conv2_kernel,
                         cudaFuncAttributeMaxDynamicSharedMemorySize, smem2);

    conv1_kernel<<<NB, 256>>>(x, c1w, c1b);
    conv2_kernel<<<NB, 288, smem2>>>(c2w, c2b);
    fc_solve_kernel<<<NB, 256>>>(x, fw, fb, out);
}

// round 3
// speedup vs baseline: 1.1441x; 1.1441x over previous
#include <cuda_runtime.h>
#include <math.h>

// ---------------------------------------------------------------------------
// QPSpeedPlanning: conv(3->32,3x3)+relu+pool2 -> conv(32->64,3x3)+relu+pool2
//                  -> FC(9219->6)+relu -> 2x2 SVD clip -> 4x4 KKT solve
// ---------------------------------------------------------------------------

#define NB 1024

__device__ float g_h1[NB * 32 * 26 * 26];   // ~88.6 MB
__device__ float g_h2[NB * 64 * 12 * 12];   // ~37.7 MB

// ---------------- conv1: 3x54x54 -> 32x26x26 (pooled) ----------------
// Task = 8 output channels x 1 pooled output (2x2 conv region, 4x4 patch).
// 2704 tasks (4 ocg x 26 x 26), 256 threads, 3 blocks/SM.
__global__ __launch_bounds__(256, 3) void conv1_kernel(
    const float* __restrict__ x, const float* __restrict__ w,
    const float* __restrict__ bias)
{
    __shared__ __align__(16) float s_in[3 * 54 * 54];   // 8748
    __shared__ float s_w[32 * 3 * 9];                    // 864
    __shared__ float s_b[32];
    int b = blockIdx.x, tid = threadIdx.x;
    const float* xb = x + b * 8751;
    for (int i = tid; i < 8748; i += 256) s_in[i] = xb[i];
    for (int i = tid; i < 864; i += 256) s_w[i] = w[i];
    if (tid < 32) s_b[tid] = bias[tid];
    __syncthreads();

    float* out = g_h1 + b * 21632;
    for (int t = tid; t < 2704; t += 256) {
        int ocg = t / 676;               // 0..3
        int rem = t - ocg * 676;
        int py = rem / 26, px = rem - py * 26;
        int y0 = 2 * py, x0 = 2 * px;

        float acc[8][4];
#pragma unroll
        for (int o = 0; o < 8; o++)
#pragma unroll
            for (int j = 0; j < 4; j++) acc[o][j] = 0.f;

#pragma unroll
        for (int ic = 0; ic < 3; ic++) {
            float p[4][4];
            const float* ip = s_in + ic * 2916 + y0 * 54 + x0;
#pragma unroll
            for (int r = 0; r < 4; r++) {
                float2 a0 = *(const float2*)(ip + r * 54);
                float2 a1 = *(const float2*)(ip + r * 54 + 2);
                p[r][0] = a0.x; p[r][1] = a0.y; p[r][2] = a1.x; p[r][3] = a1.y;
            }
#pragma unroll
            for (int o = 0; o < 8; o++) {
                const float* wp = s_w + ((ocg * 8 + o) * 3 + ic) * 9;
                float w00 = wp[0], w01 = wp[1], w02 = wp[2];
                float w10 = wp[3], w11 = wp[4], w12 = wp[5];
                float w20 = wp[6], w21 = wp[7], w22 = wp[8];
#pragma unroll
                for (int r = 0; r < 2; r++)
#pragma unroll
                    for (int c = 0; c < 2; c++) {
                        float s = acc[o][r * 2 + c];
                        s = fmaf(w00, p[r][c],     s);
                        s = fmaf(w01, p[r][c + 1], s);
                        s = fmaf(w02, p[r][c + 2], s);
                        s = fmaf(w10, p[r + 1][c],     s);
                        s = fmaf(w11, p[r + 1][c + 1], s);
                        s = fmaf(w12, p[r + 1][c + 2], s);
                        s = fmaf(w20, p[r + 2][c],     s);
                        s = fmaf(w21, p[r + 2][c + 1], s);
                        s = fmaf(w22, p[r + 2][c + 2], s);
                        acc[o][r * 2 + c] = s;
                    }
            }
        }
#pragma unroll
        for (int o = 0; o < 8; o++) {
            int oc = ocg * 8 + o;
            float m = fmaxf(fmaxf(acc[o][0], acc[o][1]),
                            fmaxf(acc[o][2], acc[o][3]));
            out[(oc * 26 + py) * 26 + px] = fmaxf(m + s_b[oc], 0.f);
        }
    }
}

// ---------------- conv2: 32x26x26 -> 64x12x12 (pooled) ----------------
// 3 spatial slices per image (pooled rows 4s..4s+3). smem: input slice
// 32x10x26 (33.3KB) + all weights (72KB) = 107KB -> 2 blocks/SM.
// 384 threads = 8 ocg x 4 rows x 12 cols, 1 task each (32 accumulators).
__global__ __launch_bounds__(384, 2) void conv2_kernel(
    const float* __restrict__ w, const float* __restrict__ bias)
{
    extern __shared__ __align__(16) float sm[];
    float* s_in = sm;                  // 8320 floats
    float* s_w  = sm + 8320;           // 18432 floats
    float* s_b  = s_w + 18432;         // 64 floats
    int s = blockIdx.x;                // slice 0..2
    int b = blockIdx.y;                // batch
    int tid = threadIdx.x;

    const float* hin = g_h1 + b * 21632;
    for (int i = tid; i < 8320; i += 384) {
        int ic = i / 260;
        int rem = i - ic * 260;
        int r = rem / 26, c = rem - r * 26;
        s_in[i] = hin[ic * 676 + (8 * s + r) * 26 + c];
    }
    for (int i = tid; i < 18432; i += 384) s_w[i] = w[i];
    if (tid < 64) s_b[tid] = bias[tid];
    __syncthreads();

    int ocg = tid / 48;                // 0..7
    int rem = tid - ocg * 48;
    int r   = rem / 12;                // pooled row within slice 0..3
    int px  = rem - r * 12;            // pooled col 0..11
    int y0 = 2 * r, x0 = 2 * px;       // relative conv/input origin

    float acc[8][4];
#pragma unroll
    for (int o = 0; o < 8; o++)
#pragma unroll
        for (int j = 0; j < 4; j++) acc[o][j] = 0.f;

#pragma unroll 1
    for (int ic = 0; ic < 32; ic++) {
        float p[4][4];
        const float* ip = s_in + ic * 260 + y0 * 26 + x0;
#pragma unroll
        for (int rr = 0; rr < 4; rr++) {
            float2 a0 = *(const float2*)(ip + rr * 26);
            float2 a1 = *(const float2*)(ip + rr * 26 + 2);
            p[rr][0] = a0.x; p[rr][1] = a0.y; p[rr][2] = a1.x; p[rr][3] = a1.y;
        }
#pragma unroll
        for (int o = 0; o < 8; o++) {
            const float* wp = s_w + ((ocg * 8 + o) * 32 + ic) * 9;
            float w00 = wp[0], w01 = wp[1], w02 = wp[2];
            float w10 = wp[3], w11 = wp[4], w12 = wp[5];
            float w20 = wp[6], w21 = wp[7], w22 = wp[8];
#pragma unroll
            for (int rr = 0; rr < 2; rr++)
#pragma unroll
                for (int c = 0; c < 2; c++) {
                    float v = acc[o][rr * 2 + c];
                    v = fmaf(w00, p[rr][c],     v);
                    v = fmaf(w01, p[rr][c + 1], v);
                    v = fmaf(w02, p[rr][c + 2], v);
                    v = fmaf(w10, p[rr + 1][c],     v);
                    v = fmaf(w11, p[rr + 1][c + 1], v);
                    v = fmaf(w12, p[rr + 1][c + 2], v);
                    v = fmaf(w20, p[rr + 2][c],     v);
                    v = fmaf(w21, p[rr + 2][c + 1], v);
                    v = fmaf(w22, p[rr + 2][c + 2], v);
                    acc[o][rr * 2 + c] = v;
                }
        }
    }

    float* out = g_h2 + b * 9216;
    int prow = 4 * s + r;
#pragma unroll
    for (int o = 0; o < 8; o++) {
        int oc = ocg * 8 + o;
        float m = fmaxf(fmaxf(acc[o][0], acc[o][1]),
                        fmaxf(acc[o][2], acc[o][3]));
        out[(oc * 12 + prow) * 12 + px] = fmaxf(m + s_b[oc], 0.f);
    }
}

// ---------------- FC + relu + SVD-clip + KKT solve ----------------
__global__ __launch_bounds__(256, 4) void fc_solve_kernel(
    const float* __restrict__ x, const float* __restrict__ fw,
    const float* __restrict__ fb, float* __restrict__ out)
{
    int b = blockIdx.x, tid = threadIdx.x;
    const float* h2 = g_h2 + b * 9216;
    float p[6] = {0.f, 0.f, 0.f, 0.f, 0.f, 0.f};
    for (int j = tid; j < 9216; j += 256) {
        float hv = h2[j];
#pragma unroll
        for (int o = 0; o < 6; o++)
            p[o] = fmaf(hv, fw[o * 9219 + j], p[o]);
    }
#pragma unroll
    for (int o = 0; o < 6; o++)
#pragma unroll
        for (int off = 16; off > 0; off >>= 1)
            p[o] += __shfl_down_sync(0xffffffffu, p[o], off);

    __shared__ float red[8][6];
    int warp = tid >> 5, lane = tid & 31;
    if (lane == 0) {
#pragma unroll
        for (int o = 0; o < 6; o++) red[warp][o] = p[o];
    }
    __syncthreads();

    if (tid == 0) {
        float y[6];
#pragma unroll
        for (int o = 0; o < 6; o++) {
            float sacc = 0.f;
            for (int wi = 0; wi < 8; wi++) sacc += red[wi][o];
            for (int e = 0; e < 3; e++)
                sacc = fmaf(x[b * 8751 + 8748 + e], fw[o * 9219 + 9216 + e], sacc);
            sacc += fb[o];
            y[o] = fmaxf(sacc, 0.f);
        }

        double a11 = y[0], a12 = y[1], a21 = y[2], a22 = y[3];
        double bb1 = y[4], bb2 = y[5];

        // Closed-form 2x2 SVD in rotation form: A = R(ph) diag(sx, sy) R(th)
        double E = 0.5 * (a11 + a22), F = 0.5 * (a11 - a22);
        double G = 0.5 * (a21 + a12), H = 0.5 * (a21 - a12);
        double Qv = sqrt(E * E + H * H), Rv = sqrt(F * F + G * G);
        double sx = Qv + Rv, sy = Qv - Rv;

        double B11, B12, B21, B22;
        if (sx <= 0.0) {
            B11 = 0.01; B22 = 0.01; B12 = 0.0; B21 = 0.0;
        } else {
            double sig2 = fabs(sy);
            double lo = 0.1 * sx;
            double c2 = sig2 < lo ? lo : sig2;
            double s2 = (sy < 0.0) ? -c2 : c2;
            double ag1 = atan2(G, F), ag2 = atan2(H, E);
            double th = 0.5 * (ag2 - ag1), ph = 0.5 * (ag2 + ag1);
            double ct = cos(th), st = sin(th), cp = cos(ph), sp = sin(ph);
            B11 =  cp * sx * ct - sp * s2 * st;
            B12 = -cp * sx * st - sp * s2 * ct;
            B21 =  sp * sx * ct + cp * s2 * st;
            B22 = -sp * sx * st + cp * s2 * ct;
        }

        // KKT via Schur complement. Q = diag(1, 0.5), p = (0, -1000)
        double K11 = B11 * B11 + 2.0 * B12 * B12;
        double K12 = B11 * B21 + 2.0 * B12 * B22;
        double K22 = B21 * B21 + 2.0 * B22 * B22;
        double w1 = 2000.0 * B12 - bb1;
        double w2 = 2000.0 * B22 - bb2;
        double det = K11 * K22 - K12 * K12;
        double l1 = (K22 * w1 - K12 * w2) / det;
        double l2 = (K11 * w2 - K12 * w1) / det;
        double z1 = -(B11 * l1 + B21 * l2);
        double z2 = 2.0 * (1000.0 - (B12 * l1 + B22 * l2));
        out[b * 2 + 0] = (float)z1;
        out[b * 2 + 1] = (float)z2;
    }
}

extern "C" void kernel_launch(void* const* d_in, const int* in_sizes, int n_in,
                              void* d_out, int out_size) {
    const float* x   = (const float*)d_in[0];
    const float* c1w = (const float*)d_in[1];
    const float* c1b = (const float*)d_in[2];
    const float* c2w = (const float*)d_in[3];
    const float* c2b = (const float*)d_in[4];
    const float* fw  = (const float*)d_in[5];
    const float* fb  = (const float*)d_in[6];
    float* out = (float*)d_out;

    const int smem2 = (8320 + 18432 + 64) * (int)sizeof(float);  // 107,264 B
    cudaFuncSetAttribute((const void*)conv2_kernel,
                         cudaFuncAttributeMaxDynamicSharedMemorySize, smem2);

    conv1_kernel<<<NB, 256>>>(x, c1w, c1b);
    conv2_kernel<<<dim3(3, NB), 384, smem2>>>(c2w, c2b);
    fc_solve_kernel<<<NB, 256>>>(x, fw, fb, out);
}